// round 3
// baseline (speedup 1.0000x reference)
#include <cuda_runtime.h>
#include <math.h>

// ---------------- problem constants ----------------
#define Bsz    16
#define CIN    103
#define HW     9
#define CCONV  256
#define NOUT   103
#define DOUT   16
#define RECN   8343            // 9*9*103
#define H1N    5562
#define H2N    12514
#define F0N    1648            // NOUT*DOUT

// ---------------- scratch (device globals; no allocation) ----------------
__device__ float g_wT[927 * 256];            // transposed conv weights [e=ci*9+k][co]
__device__ float g_Wsum[CCONV * NOUT * DOUT];// sum over prim axis of W_caps
__device__ float g_part[Bsz * 8 * CCONV * 49]; // conv partial sums per ci-chunk
__device__ float g_sq[Bsz * CCONV];          // squashed primary caps
__device__ float g_bij[NOUT * CCONV];        // routing logits [j][c]
__device__ float g_sj[Bsz * NOUT * DOUT];
__device__ float g_v[Bsz * NOUT * DOUT];
__device__ float g_f0[Bsz * F0N];
__device__ float g_f1[Bsz * H1N];
__device__ float g_f2[Bsz * H2N];
__device__ float g_fcpart[13 * Bsz * H2N];   // k-split partials (max S=13, max N=12514)

// ---------------- kernels ----------------

__global__ void k_transpose_w(const float* __restrict__ w) {
    int idx = blockIdx.x * 256 + threadIdx.x;        // 927*256 = 237312
    if (idx < 927 * 256) {
        int e = idx >> 8, co = idx & 255;
        g_wT[idx] = w[co * 927 + e];
    }
}

__global__ void k_wsum(const float* __restrict__ Wc) {
    int idx = blockIdx.x * 256 + threadIdx.x;        // 256*103*16 = 421888
    if (idx < CCONV * NOUT * DOUT) {
        const float4* p = (const float4*)(Wc + (size_t)idx * 32);
        float s = 0.f;
#pragma unroll
        for (int i = 0; i < 8; i++) {
            float4 v = p[i];
            s += v.x + v.y + v.z + v.w;
        }
        g_Wsum[idx] = s;
    }
}

__global__ void k_initb() {
    int idx = blockIdx.x * 256 + threadIdx.x;
    if (idx < NOUT * CCONV) g_bij[idx] = 1.0f;
}

// conv partial sums: grid (8 ci-chunks, 16 batch), 256 threads = co
__global__ void __launch_bounds__(256) k_conv(const float* __restrict__ x) {
    int chunk = blockIdx.x, b = blockIdx.y;
    int ci0 = chunk * 13;
    int cnt = min(13, CIN - ci0);
    __shared__ float xs[13 * 81];
    const float* xp = x + (b * CIN + ci0) * 81;
    for (int i = threadIdx.x; i < cnt * 81; i += 256) xs[i] = xp[i];
    __syncthreads();

    int co = threadIdx.x;
    float acc[49];
#pragma unroll
    for (int p = 0; p < 49; p++) acc[p] = 0.f;

    for (int cl = 0; cl < cnt; cl++) {
        float wreg[9];
#pragma unroll
        for (int k = 0; k < 9; k++) wreg[k] = g_wT[((ci0 + cl) * 9 + k) * 256 + co];
        const float* xr0 = &xs[cl * 81];
#pragma unroll
        for (int r = 0; r < 9; r++) {
            float xr[9];
#pragma unroll
            for (int q = 0; q < 9; q++) xr[q] = xr0[r * 9 + q];
#pragma unroll
            for (int kh = 0; kh < 3; kh++) {
                int ph = r - kh;
                if (ph >= 0 && ph < 7) {
#pragma unroll
                    for (int pw = 0; pw < 7; pw++) {
#pragma unroll
                        for (int kw = 0; kw < 3; kw++)
                            acc[ph * 7 + pw] = fmaf(wreg[kh * 3 + kw], xr[pw + kw], acc[ph * 7 + pw]);
                    }
                }
            }
        }
    }
    float* outp = &g_part[((b * 8 + chunk) * 256 + co) * 49];
#pragma unroll
    for (int p = 0; p < 49; p++) outp[p] = acc[p];
}

// sum chunks + bias + relu + mean + squash over channels
__global__ void k_squash_p(const float* __restrict__ conv_b) {
    int b = blockIdx.x;
    int co = threadIdx.x;
    float bias = conv_b[co];
    const float* pp = &g_part[(b * 8) * 256 * 49 + co * 49];
    float acc = 0.f;
    for (int pix = 0; pix < 49; pix++) {
        float s = bias;
#pragma unroll
        for (int ch = 0; ch < 8; ch++) s += pp[ch * (256 * 49) + pix];
        acc += fmaxf(s, 0.f);
    }
    float p = acc * (1.f / 49.f);

    __shared__ float red[256];
    red[co] = p * p;
    __syncthreads();
    for (int st = 128; st > 0; st >>= 1) {
        if (co < st) red[co] += red[co + st];
        __syncthreads();
    }
    float msq = red[0];
    float sq = p * msq / ((1.f + msq) * sqrtf(msq));
    g_sq[b * 256 + co] = sq;
}

// softmax over c (per j) + s_j : grid 103 (=j), 256 threads
__global__ void k_route_sj() {
    int j = blockIdx.x;
    int t = threadIdx.x;
    __shared__ float cs[256];
    __shared__ float sqs[16 * 256];
    __shared__ float red[256];

    float bv = g_bij[j * 256 + t];
    red[t] = bv;
    __syncthreads();
    for (int st = 128; st > 0; st >>= 1) {
        if (t < st) red[t] = fmaxf(red[t], red[t + st]);
        __syncthreads();
    }
    float mx = red[0];
    __syncthreads();
    float e = expf(bv - mx);
    red[t] = e;
    __syncthreads();
    for (int st = 128; st > 0; st >>= 1) {
        if (t < st) red[t] += red[t + st];
        __syncthreads();
    }
    float denom = red[0];
    cs[t] = e / denom;
    for (int i = t; i < 16 * 256; i += 256) sqs[i] = g_sq[i];
    __syncthreads();

    int b = t >> 4, o = t & 15;
    const float* wp = &g_Wsum[j * 16 + o];   // stride per c = 103*16
    const float* sqb = &sqs[b * 256];
    float acc = 0.f;
    for (int c = 0; c < 256; c++)
        acc = fmaf(cs[c] * sqb[c], wp[c * (NOUT * DOUT)], acc);
    g_sj[(b * NOUT + j) * DOUT + o] = acc;
}

// squash s_j over j (per b,o): grid 16 (=b), 256 threads
__global__ void k_route_v() {
    int b = blockIdx.x;
    int t = threadIdx.x;
    int o = t & 15, part = t >> 4;
    __shared__ float red[256];
    float s = 0.f;
    for (int j = part; j < NOUT; j += 16) {
        float v = g_sj[(b * NOUT + j) * DOUT + o];
        s += v * v;
    }
    red[t] = s;
    __syncthreads();
    for (int st = 128; st >= 16; st >>= 1) {
        if (t < st) red[t] += red[t + st];
        __syncthreads();
    }
    float msq = red[o];
    float scale = msq / ((1.f + msq) * sqrtf(msq));
    for (int j = part; j < NOUT; j += 16) {
        int i = (b * NOUT + j) * DOUT + o;
        g_v[i] = scale * g_sj[i];
    }
}

// agreement + logit update: grid 103 (=j), 256 threads = c
__global__ void k_route_update() {
    int j = blockIdx.x;
    int c = threadIdx.x;
    __shared__ float vs[16 * 16];
    if (c < 256) {
        int b = c >> 4, o = c & 15;
        vs[c] = g_v[(b * NOUT + j) * DOUT + o];
    }
    __syncthreads();
    const float4* w4 = (const float4*)&g_Wsum[(c * NOUT + j) * DOUT];
    float4 wa = w4[0], wb = w4[1], wc = w4[2], wd = w4[3];
    float w[16] = {wa.x, wa.y, wa.z, wa.w, wb.x, wb.y, wb.z, wb.w,
                   wc.x, wc.y, wc.z, wc.w, wd.x, wd.y, wd.z, wd.w};
    float q = 0.f;
#pragma unroll
    for (int b = 0; b < 16; b++) {
        float dot = 0.f;
#pragma unroll
        for (int o = 0; o < 16; o++) dot = fmaf(w[o], vs[b * 16 + o], dot);
        q = fmaf(g_sq[b * 256 + c], dot, q);
    }
    g_bij[j * 256 + c] += q * (1.f / 16.f);
}

// ba (first output) + f0 = v * ||v||
__global__ void k_ba_f0(float* __restrict__ out) {
    int idx = blockIdx.x * 256 + threadIdx.x;   // 1648
    if (idx < Bsz * NOUT) {
        int b = idx / NOUT, j = idx % NOUT;
        const float* vp = &g_v[(b * NOUT + j) * DOUT];
        float msq = 0.f;
#pragma unroll
        for (int o = 0; o < 16; o++) msq = fmaf(vp[o], vp[o], msq);
        float ba = sqrtf(msq);
        out[b * NOUT + j] = ba;
        float* f0 = &g_f0[b * F0N + j * 16];
#pragma unroll
        for (int o = 0; o < 16; o++) f0[o] = vp[o] * ba;
    }
}

// GEMM: g_fcpart[s][b][n] = sum_{k in chunk s} fin[b][k] * W[k][n]
// fin selected IN DEVICE CODE (cannot pass __device__ globals from host).
// grid (ntiles, S), 256 threads; thread <-> n, 16 batch accumulators.
__global__ void __launch_bounds__(256) k_gemm(int fin_sel,
                                              const float* __restrict__ W,
                                              int N, int K, int kchunk) {
    const float* fin = (fin_sel == 0) ? g_f0 : (fin_sel == 1) ? g_f1 : g_f2;
    int s = blockIdx.y;
    int n = blockIdx.x * 256 + threadIdx.x;
    int k0 = s * kchunk;
    int k1 = min(K, k0 + kchunk);
    bool valid = (n < N);

    __shared__ float fs[128 * 16];   // [kk][b]
    float acc[16];
#pragma unroll
    for (int b = 0; b < 16; b++) acc[b] = 0.f;

    for (int kt = k0; kt < k1; kt += 128) {
        int kc = min(128, k1 - kt);
        __syncthreads();
        for (int i = threadIdx.x; i < 16 * 128; i += 256) {
            int b = i >> 7, kk = i & 127;
            if (kk < kc) fs[kk * 16 + b] = fin[b * K + kt + kk];
        }
        __syncthreads();
        if (valid) {
            const float* wp = W + (size_t)kt * N + n;
            if (kc == 128) {
#pragma unroll 8
                for (int kk = 0; kk < 128; kk++) {
                    float wv = wp[(size_t)kk * N];
                    const float4* f4 = (const float4*)&fs[kk * 16];
                    float4 a = f4[0], b4 = f4[1], c4 = f4[2], d4 = f4[3];
                    acc[0]  = fmaf(wv, a.x, acc[0]);   acc[1]  = fmaf(wv, a.y, acc[1]);
                    acc[2]  = fmaf(wv, a.z, acc[2]);   acc[3]  = fmaf(wv, a.w, acc[3]);
                    acc[4]  = fmaf(wv, b4.x, acc[4]);  acc[5]  = fmaf(wv, b4.y, acc[5]);
                    acc[6]  = fmaf(wv, b4.z, acc[6]);  acc[7]  = fmaf(wv, b4.w, acc[7]);
                    acc[8]  = fmaf(wv, c4.x, acc[8]);  acc[9]  = fmaf(wv, c4.y, acc[9]);
                    acc[10] = fmaf(wv, c4.z, acc[10]); acc[11] = fmaf(wv, c4.w, acc[11]);
                    acc[12] = fmaf(wv, d4.x, acc[12]); acc[13] = fmaf(wv, d4.y, acc[13]);
                    acc[14] = fmaf(wv, d4.z, acc[14]); acc[15] = fmaf(wv, d4.w, acc[15]);
                }
            } else {
                for (int kk = 0; kk < kc; kk++) {
                    float wv = wp[(size_t)kk * N];
                    const float4* f4 = (const float4*)&fs[kk * 16];
                    float4 a = f4[0], b4 = f4[1], c4 = f4[2], d4 = f4[3];
                    acc[0]  = fmaf(wv, a.x, acc[0]);   acc[1]  = fmaf(wv, a.y, acc[1]);
                    acc[2]  = fmaf(wv, a.z, acc[2]);   acc[3]  = fmaf(wv, a.w, acc[3]);
                    acc[4]  = fmaf(wv, b4.x, acc[4]);  acc[5]  = fmaf(wv, b4.y, acc[5]);
                    acc[6]  = fmaf(wv, b4.z, acc[6]);  acc[7]  = fmaf(wv, b4.w, acc[7]);
                    acc[8]  = fmaf(wv, c4.x, acc[8]);  acc[9]  = fmaf(wv, c4.y, acc[9]);
                    acc[10] = fmaf(wv, c4.z, acc[10]); acc[11] = fmaf(wv, c4.w, acc[11]);
                    acc[12] = fmaf(wv, d4.x, acc[12]); acc[13] = fmaf(wv, d4.y, acc[13]);
                    acc[14] = fmaf(wv, d4.z, acc[14]); acc[15] = fmaf(wv, d4.w, acc[15]);
                }
            }
        }
    }
    if (valid) {
#pragma unroll
        for (int b = 0; b < 16; b++)
            g_fcpart[(size_t)(s * 16 + b) * N + n] = acc[b];
    }
}

// deterministic k-split reduction + bias.
// out_sel: 0 -> g_f1, 1 -> g_f2, 2 -> harness out pointer (recon region)
__global__ void k_reduce(const float* __restrict__ bias,
                         int N, int S, int out_sel, float* __restrict__ hout) {
    float* out = (out_sel == 0) ? g_f1 : (out_sel == 1) ? g_f2 : hout;
    int idx = blockIdx.x * 256 + threadIdx.x;
    if (idx < 16 * N) {
        int b = idx / N, n = idx - b * N;
        float s = bias[n];
        for (int sp = 0; sp < S; sp++) s += g_fcpart[(size_t)(sp * 16 + b) * N + n];
        out[b * N + n] = s;
    }
}

// ---------------- launcher ----------------
extern "C" void kernel_launch(void* const* d_in, const int* in_sizes, int n_in,
                              void* d_out, int out_size) {
    const float* x      = (const float*)d_in[0];
    const float* conv_w = (const float*)d_in[1];
    const float* conv_b = (const float*)d_in[2];
    const float* W_caps = (const float*)d_in[3];
    const float* fc1_w  = (const float*)d_in[4];
    const float* fc1_b  = (const float*)d_in[5];
    const float* fc2_w  = (const float*)d_in[6];
    const float* fc2_b  = (const float*)d_in[7];
    const float* fc3_w  = (const float*)d_in[8];
    const float* fc3_b  = (const float*)d_in[9];
    float* out = (float*)d_out;

    (void)in_sizes; (void)n_in; (void)out_size;

    k_transpose_w<<<927, 256>>>(conv_w);
    k_wsum<<<1648, 256>>>(W_caps);
    k_initb<<<(NOUT * CCONV + 255) / 256, 256>>>();
    k_conv<<<dim3(8, 16), 256>>>(x);
    k_squash_p<<<16, 256>>>(conv_b);

    for (int it = 0; it < 3; it++) {
        k_route_sj<<<103, 256>>>();
        k_route_v<<<16, 256>>>();
        if (it < 2) k_route_update<<<103, 256>>>();
    }
    k_ba_f0<<<7, 256>>>(out);

    // fc1: (16x1648)@(1648x5562)  S=13, chunk=128
    k_gemm<<<dim3(22, 13), 256>>>(0, fc1_w, H1N, F0N, 128);
    k_reduce<<<(16 * H1N + 255) / 256, 256>>>(fc1_b, H1N, 13, 0, out);
    // fc2: (16x5562)@(5562x12514) S=6, chunk=928
    k_gemm<<<dim3(49, 6), 256>>>(1, fc2_w, H2N, H1N, 928);
    k_reduce<<<(16 * H2N + 255) / 256, 256>>>(fc2_b, H2N, 6, 1, out);
    // fc3: (16x12514)@(12514x8343) S=9, chunk=1392 ; output -> recon region
    k_gemm<<<dim3(33, 9), 256>>>(2, fc3_w, RECN, H2N, 1392);
    k_reduce<<<(16 * RECN + 255) / 256, 256>>>(fc3_b, RECN, 9, 2, out + Bsz * NOUT);
}

// round 4
// speedup vs baseline: 1.4838x; 1.4838x over previous
#include <cuda_runtime.h>
#include <math.h>

// ---------------- problem constants ----------------
#define Bsz    16
#define CIN    103
#define CCONV  256
#define NOUT   103
#define DOUT   16
#define RECN   8343            // 9*9*103
#define H1N    5562
#define H2N    12514
#define F0N    1648            // NOUT*DOUT
#define NCH    15              // conv ci-chunks (7 channels each)

// ---------------- scratch (device globals; no allocation) ----------------
__device__ float g_wT[927 * 256];              // transposed conv weights [e=ci*9+k][co]
__device__ float g_Wsum[CCONV * NOUT * DOUT];  // sum over prim axis of W_caps
__device__ float g_part[Bsz * NCH * CCONV * 49];
__device__ float g_sq[Bsz * CCONV];
__device__ float g_bij[NOUT * CCONV];
__device__ float g_sj[Bsz * NOUT * DOUT];
__device__ float g_v[Bsz * NOUT * DOUT];
__device__ float g_f0[Bsz * F0N];
__device__ float g_f1[Bsz * H1N];
__device__ float g_f2[Bsz * H2N];
__device__ float g_fcpart[17 * Bsz * H2N];     // k-split partials (max S=17)

// packed f32x2 FMA (sm_103a FFMA2 — PTX-only, ptxas never auto-fuses)
#define FMA_F32X2(acc, a, b) \
    asm("fma.rn.f32x2 %0, %1, %2, %0;" : "+l"(acc) : "l"(a), "l"(b))

// ---------------- kernels ----------------

__global__ void k_transpose_w(const float* __restrict__ w) {
    int idx = blockIdx.x * 256 + threadIdx.x;        // 927*256
    if (idx < 927 * 256) {
        int e = idx >> 8, co = idx & 255;
        g_wT[idx] = w[co * 927 + e];
    }
}

__global__ void k_wsum(const float* __restrict__ Wc) {
    int idx = blockIdx.x * 256 + threadIdx.x;        // 256*103*16
    if (idx < CCONV * NOUT * DOUT) {
        const float4* p = (const float4*)(Wc + (size_t)idx * 32);
        float s = 0.f;
#pragma unroll
        for (int i = 0; i < 8; i++) {
            float4 v = p[i];
            s += v.x + v.y + v.z + v.w;
        }
        g_Wsum[idx] = s;
    }
}

__global__ void k_initb() {
    int idx = blockIdx.x * 256 + threadIdx.x;
    if (idx < NOUT * CCONV) g_bij[idx] = 1.0f;
}

// conv partial sums: grid (NCH ci-chunks, 16 batch), 256 threads = co
__global__ void __launch_bounds__(256) k_conv(const float* __restrict__ x) {
    int chunk = blockIdx.x, b = blockIdx.y;
    int ci0 = chunk * 7;
    int cnt = min(7, CIN - ci0);
    __shared__ float xs[7 * 81];
    const float* xp = x + (b * CIN + ci0) * 81;
    for (int i = threadIdx.x; i < cnt * 81; i += 256) xs[i] = xp[i];
    __syncthreads();

    int co = threadIdx.x;
    float acc[49];
#pragma unroll
    for (int p = 0; p < 49; p++) acc[p] = 0.f;

    for (int cl = 0; cl < cnt; cl++) {
        float wreg[9];
#pragma unroll
        for (int k = 0; k < 9; k++) wreg[k] = g_wT[((ci0 + cl) * 9 + k) * 256 + co];
        const float* xr0 = &xs[cl * 81];
#pragma unroll
        for (int r = 0; r < 9; r++) {
            float xr[9];
#pragma unroll
            for (int q = 0; q < 9; q++) xr[q] = xr0[r * 9 + q];
#pragma unroll
            for (int kh = 0; kh < 3; kh++) {
                int ph = r - kh;
                if (ph >= 0 && ph < 7) {
#pragma unroll
                    for (int pw = 0; pw < 7; pw++) {
#pragma unroll
                        for (int kw = 0; kw < 3; kw++)
                            acc[ph * 7 + pw] = fmaf(wreg[kh * 3 + kw], xr[pw + kw], acc[ph * 7 + pw]);
                    }
                }
            }
        }
    }
    float* outp = &g_part[((b * NCH + chunk) * 256 + co) * 49];
#pragma unroll
    for (int p = 0; p < 49; p++) outp[p] = acc[p];
}

// sum chunks + bias + relu + mean + squash over channels
__global__ void k_squash_p(const float* __restrict__ conv_b) {
    int b = blockIdx.x;
    int co = threadIdx.x;
    float bias = conv_b[co];
    const float* pp = &g_part[(size_t)(b * NCH) * 256 * 49 + co * 49];
    float acc = 0.f;
    for (int pix = 0; pix < 49; pix++) {
        float s = bias;
#pragma unroll
        for (int ch = 0; ch < NCH; ch++) s += pp[(size_t)ch * (256 * 49) + pix];
        acc += fmaxf(s, 0.f);
    }
    float p = acc * (1.f / 49.f);

    __shared__ float red[256];
    red[co] = p * p;
    __syncthreads();
    for (int st = 128; st > 0; st >>= 1) {
        if (co < st) red[co] += red[co + st];
        __syncthreads();
    }
    float msq = red[0];
    float sq = p * msq / ((1.f + msq) * sqrtf(msq));
    g_sq[b * 256 + co] = sq;
}

// softmax over c (per j) + s_j : grid 103 (=j), 256 threads. SMEM-staged Wsum.
__global__ void __launch_bounds__(256) k_route_sj() {
    int j = blockIdx.x;
    int t = threadIdx.x;
    __shared__ float cs[256];
    __shared__ float csq[16 * 256];   // c_ij[c] * sq[b][c]
    __shared__ float ws[256 * 16];    // Wsum[c][j][:] slice, [c][o]
    __shared__ float red[256];

    float bv = g_bij[j * 256 + t];
    red[t] = bv;
    __syncthreads();
    for (int st = 128; st > 0; st >>= 1) {
        if (t < st) red[t] = fmaxf(red[t], red[t + st]);
        __syncthreads();
    }
    float mx = red[0];
    __syncthreads();
    float e = expf(bv - mx);
    red[t] = e;
    __syncthreads();
    for (int st = 128; st > 0; st >>= 1) {
        if (t < st) red[t] += red[t + st];
        __syncthreads();
    }
    float denom = red[0];
    cs[t] = e / denom;
    // stage Wsum slice for this j: ws[c*16+o]
    for (int i = t; i < 256 * 16; i += 256) {
        int c = i >> 4, o = i & 15;
        ws[i] = g_Wsum[c * (NOUT * DOUT) + j * DOUT + o];
    }
    __syncthreads();
    // csq[b][c] = cs[c] * sq[b][c]
    for (int i = t; i < 16 * 256; i += 256)
        csq[i] = cs[i & 255] * g_sq[i];
    __syncthreads();

    int b = t >> 4, o = t & 15;
    const float* cq = &csq[b * 256];
    float acc = 0.f;
#pragma unroll 8
    for (int c = 0; c < 256; c++)
        acc = fmaf(cq[c], ws[c * 16 + o], acc);
    g_sj[(b * NOUT + j) * DOUT + o] = acc;
}

// squash s_j over j (per b,o): grid 16 (=b), 256 threads
__global__ void k_route_v() {
    int b = blockIdx.x;
    int t = threadIdx.x;
    int o = t & 15, part = t >> 4;
    __shared__ float red[256];
    float s = 0.f;
    for (int j = part; j < NOUT; j += 16) {
        float v = g_sj[(b * NOUT + j) * DOUT + o];
        s += v * v;
    }
    red[t] = s;
    __syncthreads();
    for (int st = 128; st >= 16; st >>= 1) {
        if (t < st) red[t] += red[t + st];
        __syncthreads();
    }
    float msq = red[o];
    float scale = msq / ((1.f + msq) * sqrtf(msq));
    for (int j = part; j < NOUT; j += 16) {
        int i = (b * NOUT + j) * DOUT + o;
        g_v[i] = scale * g_sj[i];
    }
}

// agreement + logit update: grid 103 (=j), 256 threads = c
__global__ void k_route_update() {
    int j = blockIdx.x;
    int c = threadIdx.x;
    __shared__ float vs[16 * 16];
    if (c < 256) {
        int b = c >> 4, o = c & 15;
        vs[c] = g_v[(b * NOUT + j) * DOUT + o];
    }
    __syncthreads();
    const float4* w4 = (const float4*)&g_Wsum[(c * NOUT + j) * DOUT];
    float4 wa = w4[0], wb = w4[1], wc = w4[2], wd = w4[3];
    float w[16] = {wa.x, wa.y, wa.z, wa.w, wb.x, wb.y, wb.z, wb.w,
                   wc.x, wc.y, wc.z, wc.w, wd.x, wd.y, wd.z, wd.w};
    float q = 0.f;
#pragma unroll
    for (int b = 0; b < 16; b++) {
        float dot = 0.f;
#pragma unroll
        for (int o = 0; o < 16; o++) dot = fmaf(w[o], vs[b * 16 + o], dot);
        q = fmaf(g_sq[b * 256 + c], dot, q);
    }
    g_bij[j * 256 + c] += q * (1.f / 16.f);
}

// ba (first output) + f0 = v * ||v||
__global__ void k_ba_f0(float* __restrict__ out) {
    int idx = blockIdx.x * 256 + threadIdx.x;   // 1648
    if (idx < Bsz * NOUT) {
        int b = idx / NOUT, j = idx % NOUT;
        const float* vp = &g_v[(b * NOUT + j) * DOUT];
        float msq = 0.f;
#pragma unroll
        for (int o = 0; o < 16; o++) msq = fmaf(vp[o], vp[o], msq);
        float ba = sqrtf(msq);
        out[b * NOUT + j] = ba;
        float* f0 = &g_f0[b * F0N + j * 16];
#pragma unroll
        for (int o = 0; o < 16; o++) f0[o] = vp[o] * ba;
    }
}

// GEMM with packed f32x2 FMAs.
// g_fcpart[s][b][n] = sum_{k in chunk s} fin[b][k] * W[k][n]
// grid (ntiles, S), 256 threads; thread <-> n, 8 packed (=16) batch accumulators.
__global__ void __launch_bounds__(256) k_gemm(int fin_sel,
                                              const float* __restrict__ W,
                                              int N, int K, int kchunk) {
    const float* fin = (fin_sel == 0) ? g_f0 : (fin_sel == 1) ? g_f1 : g_f2;
    int s = blockIdx.y;
    int n = blockIdx.x * 256 + threadIdx.x;
    int k0 = s * kchunk;
    int k1 = min(K, k0 + kchunk);
    bool valid = (n < N);

    __shared__ float fs[128 * 16];   // [kk][b], 16B aligned
    unsigned long long acc[8];
#pragma unroll
    for (int p = 0; p < 8; p++) acc[p] = 0ull;

    for (int kt = k0; kt < k1; kt += 128) {
        int kc = min(128, k1 - kt);
        __syncthreads();
        for (int i = threadIdx.x; i < 16 * 128; i += 256) {
            int b = i >> 7, kk = i & 127;
            if (kk < kc) fs[kk * 16 + b] = fin[b * K + kt + kk];
        }
        __syncthreads();
        if (valid) {
            const float* wp = W + (size_t)kt * N + n;
            if (kc == 128) {
#pragma unroll 8
                for (int kk = 0; kk < 128; kk++) {
                    float wv = wp[(size_t)kk * N];
                    unsigned long long w2;
                    asm("mov.b64 %0, {%1, %1};" : "=l"(w2) : "f"(wv));
                    const unsigned long long* f2 =
                        (const unsigned long long*)&fs[kk * 16];
                    FMA_F32X2(acc[0], w2, f2[0]);
                    FMA_F32X2(acc[1], w2, f2[1]);
                    FMA_F32X2(acc[2], w2, f2[2]);
                    FMA_F32X2(acc[3], w2, f2[3]);
                    FMA_F32X2(acc[4], w2, f2[4]);
                    FMA_F32X2(acc[5], w2, f2[5]);
                    FMA_F32X2(acc[6], w2, f2[6]);
                    FMA_F32X2(acc[7], w2, f2[7]);
                }
            } else {
                for (int kk = 0; kk < kc; kk++) {
                    float wv = wp[(size_t)kk * N];
                    unsigned long long w2;
                    asm("mov.b64 %0, {%1, %1};" : "=l"(w2) : "f"(wv));
                    const unsigned long long* f2 =
                        (const unsigned long long*)&fs[kk * 16];
#pragma unroll
                    for (int p = 0; p < 8; p++) FMA_F32X2(acc[p], w2, f2[p]);
                }
            }
        }
    }
    if (valid) {
#pragma unroll
        for (int p = 0; p < 8; p++) {
            float lo = __uint_as_float((unsigned int)acc[p]);
            float hi = __uint_as_float((unsigned int)(acc[p] >> 32));
            g_fcpart[(size_t)(s * 16 + 2 * p + 0) * N + n] = lo;
            g_fcpart[(size_t)(s * 16 + 2 * p + 1) * N + n] = hi;
        }
    }
}

// deterministic k-split reduction + bias.
// out_sel: 0 -> g_f1, 1 -> g_f2, 2 -> harness out pointer (recon region)
__global__ void k_reduce(const float* __restrict__ bias,
                         int N, int S, int out_sel, float* __restrict__ hout) {
    float* out = (out_sel == 0) ? g_f1 : (out_sel == 1) ? g_f2 : hout;
    int idx = blockIdx.x * 256 + threadIdx.x;
    if (idx < 16 * N) {
        int b = idx / N, n = idx - b * N;
        float s = bias[n];
        for (int sp = 0; sp < S; sp++) s += g_fcpart[(size_t)(sp * 16 + b) * N + n];
        out[b * N + n] = s;
    }
}

// ---------------- launcher ----------------
extern "C" void kernel_launch(void* const* d_in, const int* in_sizes, int n_in,
                              void* d_out, int out_size) {
    const float* x      = (const float*)d_in[0];
    const float* conv_w = (const float*)d_in[1];
    const float* conv_b = (const float*)d_in[2];
    const float* W_caps = (const float*)d_in[3];
    const float* fc1_w  = (const float*)d_in[4];
    const float* fc1_b  = (const float*)d_in[5];
    const float* fc2_w  = (const float*)d_in[6];
    const float* fc2_b  = (const float*)d_in[7];
    const float* fc3_w  = (const float*)d_in[8];
    const float* fc3_b  = (const float*)d_in[9];
    float* out = (float*)d_out;

    (void)in_sizes; (void)n_in; (void)out_size;

    k_transpose_w<<<927, 256>>>(conv_w);
    k_wsum<<<1648, 256>>>(W_caps);
    k_initb<<<(NOUT * CCONV + 255) / 256, 256>>>();
    k_conv<<<dim3(NCH, 16), 256>>>(x);
    k_squash_p<<<16, 256>>>(conv_b);

    for (int it = 0; it < 3; it++) {
        k_route_sj<<<103, 256>>>();
        k_route_v<<<16, 256>>>();
        if (it < 2) k_route_update<<<103, 256>>>();
    }
    k_ba_f0<<<7, 256>>>(out);

    // fc1: (16x1648)@(1648x5562)   S=13, chunk=128  -> 286 blocks
    k_gemm<<<dim3(22, 13), 256>>>(0, fc1_w, H1N, F0N, 128);
    k_reduce<<<(16 * H1N + 255) / 256, 256>>>(fc1_b, H1N, 13, 0, out);
    // fc2: (16x5562)@(5562x12514)  S=11, chunk=512  -> 539 blocks
    k_gemm<<<dim3(49, 11), 256>>>(1, fc2_w, H2N, H1N, 512);
    k_reduce<<<(16 * H2N + 255) / 256, 256>>>(fc2_b, H2N, 11, 1, out);
    // fc3: (16x12514)@(12514x8343) S=17, chunk=768  -> 561 blocks
    k_gemm<<<dim3(33, 17), 256>>>(2, fc3_w, RECN, H2N, 768);
    k_reduce<<<(16 * RECN + 255) / 256, 256>>>(fc3_b, RECN, 17, 2, out + Bsz * NOUT);
}

// round 7
// speedup vs baseline: 1.8797x; 1.2669x over previous
#include <cuda_runtime.h>
#include <math.h>

// ---------------- problem constants ----------------
#define Bsz    16
#define CIN    103
#define CCONV  256
#define NOUT   103
#define DOUT   16
#define RECN   8343            // 9*9*103
#define H1N    5562
#define H2N    12514
#define F0N    1648            // NOUT*DOUT
#define NCH    15              // conv ci-chunks (7 channels each)

// ---------------- scratch (device globals; no allocation) ----------------
__device__ float g_wT[927 * 256];              // transposed conv weights [e=ci*9+k][co]
__device__ float g_Wsum[CCONV * NOUT * DOUT];  // sum over prim axis of W_caps
__device__ float g_part[Bsz * NCH * CCONV * 49];
__device__ float g_hsum[Bsz * CCONV * 49];     // relu'd conv activations
__device__ float g_sq[Bsz * CCONV];
__device__ float g_bij[NOUT * CCONV];
__device__ float g_sj[Bsz * NOUT * DOUT];
__device__ float g_v[Bsz * NOUT * DOUT];
__device__ float g_f0[Bsz * F0N];
__device__ float g_f1[Bsz * H1N];
__device__ float g_f2[Bsz * H2N];
__device__ float g_fcpart[23 * Bsz * H2N];     // k-split partials (max S=23 @ N=12514)

// packed f32x2 FMA (sm_103a FFMA2 — PTX-only, ptxas never auto-fuses)
#define FMA_F32X2(acc, a, b) \
    asm("fma.rn.f32x2 %0, %1, %2, %0;" : "+l"(acc) : "l"(a), "l"(b))

// ---------------- small prep kernels ----------------

__global__ void k_transpose_w(const float* __restrict__ w) {
    int idx = blockIdx.x * 256 + threadIdx.x;        // 927*256
    if (idx < 927 * 256) {
        int e = idx >> 8, co = idx & 255;
        g_wT[idx] = w[co * 927 + e];
    }
}

__global__ void k_wsum(const float* __restrict__ Wc) {
    int idx = blockIdx.x * 256 + threadIdx.x;        // 256*103*16
    if (idx < CCONV * NOUT * DOUT) {
        const float4* p = (const float4*)(Wc + (size_t)idx * 32);
        float s = 0.f;
#pragma unroll
        for (int i = 0; i < 8; i++) {
            float4 v = p[i];
            s += v.x + v.y + v.z + v.w;
        }
        g_Wsum[idx] = s;
    }
}

__global__ void k_initb() {
    int idx = blockIdx.x * 256 + threadIdx.x;
    if (idx < NOUT * CCONV) g_bij[idx] = 1.0f;
}

// ---------------- conv ----------------
// partial sums: grid (NCH ci-chunks, 16 batch), 256 threads = co
// weight double-buffer: prefetch next channel's 9 weights during compute
__global__ void __launch_bounds__(256) k_conv(const float* __restrict__ x) {
    int chunk = blockIdx.x, b = blockIdx.y;
    int ci0 = chunk * 7;
    int cnt = min(7, CIN - ci0);
    __shared__ float xs[7 * 81];
    const float* xp = x + (b * CIN + ci0) * 81;
    for (int i = threadIdx.x; i < cnt * 81; i += 256) xs[i] = xp[i];
    __syncthreads();

    int co = threadIdx.x;
    float acc[49];
#pragma unroll
    for (int p = 0; p < 49; p++) acc[p] = 0.f;

    float wA[9], wB[9];
#pragma unroll
    for (int k = 0; k < 9; k++) wA[k] = g_wT[(ci0 * 9 + k) * 256 + co];

    for (int cl = 0; cl < cnt; cl++) {
        if (cl + 1 < cnt) {
#pragma unroll
            for (int k = 0; k < 9; k++)
                wB[k] = g_wT[((ci0 + cl + 1) * 9 + k) * 256 + co];
        }
        const float* xr0 = &xs[cl * 81];
#pragma unroll
        for (int r = 0; r < 9; r++) {
            float xr[9];
#pragma unroll
            for (int q = 0; q < 9; q++) xr[q] = xr0[r * 9 + q];
#pragma unroll
            for (int kh = 0; kh < 3; kh++) {
                int ph = r - kh;
                if (ph >= 0 && ph < 7) {
#pragma unroll
                    for (int pw = 0; pw < 7; pw++) {
#pragma unroll
                        for (int kw = 0; kw < 3; kw++)
                            acc[ph * 7 + pw] = fmaf(wA[kh * 3 + kw], xr[pw + kw], acc[ph * 7 + pw]);
                    }
                }
            }
        }
#pragma unroll
        for (int k = 0; k < 9; k++) wA[k] = wB[k];
    }
    float* outp = &g_part[((b * NCH + chunk) * 256 + co) * 49];
#pragma unroll
    for (int p = 0; p < 49; p++) outp[p] = acc[p];
}

// wide chunk-sum + bias + relu: one thread per (b,co,pix) = 200704
__global__ void k_relu_sum(const float* __restrict__ conv_b) {
    int idx = blockIdx.x * 256 + threadIdx.x;
    if (idx < Bsz * CCONV * 49) {
        int pix = idx % 49;
        int co  = (idx / 49) & 255;
        int b   = idx / (49 * 256);
        float s = conv_b[co];
#pragma unroll
        for (int ch = 0; ch < NCH; ch++)
            s += g_part[(size_t)((b * NCH + ch) * 256 + co) * 49 + pix];
        g_hsum[idx] = fmaxf(s, 0.f);
    }
}

// mean over pixels + squash over channels
__global__ void k_squash_p() {
    int b = blockIdx.x;
    int co = threadIdx.x;
    const float* hp = &g_hsum[(b * 256 + co) * 49];
    float acc = 0.f;
#pragma unroll
    for (int pix = 0; pix < 49; pix++) acc += hp[pix];
    float p = acc * (1.f / 49.f);

    __shared__ float red[256];
    red[co] = p * p;
    __syncthreads();
    for (int st = 128; st > 0; st >>= 1) {
        if (co < st) red[co] += red[co + st];
        __syncthreads();
    }
    float msq = red[0];
    float sq = p * msq / ((1.f + msq) * sqrtf(msq));
    g_sq[b * 256 + co] = sq;
}

// ---------------- routing ----------------

__global__ void __launch_bounds__(256) k_route_sj() {
    int j = blockIdx.x;
    int t = threadIdx.x;
    __shared__ float cs[256];
    __shared__ float csq[16 * 256];
    __shared__ float ws[256 * 16];
    __shared__ float red[256];

    float bv = g_bij[j * 256 + t];
    red[t] = bv;
    __syncthreads();
    for (int st = 128; st > 0; st >>= 1) {
        if (t < st) red[t] = fmaxf(red[t], red[t + st]);
        __syncthreads();
    }
    float mx = red[0];
    __syncthreads();
    float e = expf(bv - mx);
    red[t] = e;
    __syncthreads();
    for (int st = 128; st > 0; st >>= 1) {
        if (t < st) red[t] += red[t + st];
        __syncthreads();
    }
    float denom = red[0];
    cs[t] = e / denom;
    for (int i = t; i < 256 * 16; i += 256) {
        int c = i >> 4, o = i & 15;
        ws[i] = g_Wsum[c * (NOUT * DOUT) + j * DOUT + o];
    }
    __syncthreads();
    for (int i = t; i < 16 * 256; i += 256)
        csq[i] = cs[i & 255] * g_sq[i];
    __syncthreads();

    int b = t >> 4, o = t & 15;
    const float* cq = &csq[b * 256];
    float acc = 0.f;
#pragma unroll 8
    for (int c = 0; c < 256; c++)
        acc = fmaf(cq[c], ws[c * 16 + o], acc);
    g_sj[(b * NOUT + j) * DOUT + o] = acc;
}

__global__ void k_route_v() {
    int b = blockIdx.x;
    int t = threadIdx.x;
    int o = t & 15, part = t >> 4;
    __shared__ float red[256];
    float s = 0.f;
    for (int j = part; j < NOUT; j += 16) {
        float v = g_sj[(b * NOUT + j) * DOUT + o];
        s += v * v;
    }
    red[t] = s;
    __syncthreads();
    for (int st = 128; st >= 16; st >>= 1) {
        if (t < st) red[t] += red[t + st];
        __syncthreads();
    }
    float msq = red[o];
    float scale = msq / ((1.f + msq) * sqrtf(msq));
    for (int j = part; j < NOUT; j += 16) {
        int i = (b * NOUT + j) * DOUT + o;
        g_v[i] = scale * g_sj[i];
    }
}

__global__ void k_route_update() {
    int j = blockIdx.x;
    int c = threadIdx.x;
    __shared__ float vs[16 * 16];
    if (c < 256) {
        int b = c >> 4, o = c & 15;
        vs[c] = g_v[(b * NOUT + j) * DOUT + o];
    }
    __syncthreads();
    const float4* w4 = (const float4*)&g_Wsum[(c * NOUT + j) * DOUT];
    float4 wa = w4[0], wb = w4[1], wc = w4[2], wd = w4[3];
    float w[16] = {wa.x, wa.y, wa.z, wa.w, wb.x, wb.y, wb.z, wb.w,
                   wc.x, wc.y, wc.z, wc.w, wd.x, wd.y, wd.z, wd.w};
    float q = 0.f;
#pragma unroll
    for (int b = 0; b < 16; b++) {
        float dot = 0.f;
#pragma unroll
        for (int o = 0; o < 16; o++) dot = fmaf(w[o], vs[b * 16 + o], dot);
        q = fmaf(g_sq[b * 256 + c], dot, q);
    }
    g_bij[j * 256 + c] += q * (1.f / 16.f);
}

__global__ void k_ba_f0(float* __restrict__ out) {
    int idx = blockIdx.x * 256 + threadIdx.x;   // 1648
    if (idx < Bsz * NOUT) {
        int b = idx / NOUT, j = idx % NOUT;
        const float* vp = &g_v[(b * NOUT + j) * DOUT];
        float msq = 0.f;
#pragma unroll
        for (int o = 0; o < 16; o++) msq = fmaf(vp[o], vp[o], msq);
        float ba = sqrtf(msq);
        out[b * NOUT + j] = ba;
        float* f0 = &g_f0[b * F0N + j * 16];
#pragma unroll
        for (int o = 0; o < 16; o++) f0[o] = vp[o] * ba;
    }
}

// ---------------- FC GEMM ----------------
// 4 columns per thread (stride 256), 16 batches -> 32 u64 FMA2 accumulators.
// g_fcpart[s][b][n] = sum_{k in chunk s} fin[b][k] * W[k][n]
__global__ void __launch_bounds__(256, 2) k_gemm4(int fin_sel,
                                                  const float* __restrict__ W,
                                                  int N, int K, int kchunk) {
    const float* fin = (fin_sel == 0) ? g_f0 : (fin_sel == 1) ? g_f1 : g_f2;
    int s = blockIdx.y;
    int nb = blockIdx.x * 1024 + threadIdx.x;
    int k0 = s * kchunk;
    int k1 = min(K, k0 + kchunk);

    int nc[4];
    bool vld[4];
#pragma unroll
    for (int c = 0; c < 4; c++) {
        int n = nb + c * 256;
        vld[c] = (n < N);
        nc[c] = vld[c] ? n : 0;    // clamp keeps loads in-bounds; store guarded
    }

    __shared__ float fs[128 * 16];   // [kk][b]
    unsigned long long acc[32];
#pragma unroll
    for (int p = 0; p < 32; p++) acc[p] = 0ull;

    for (int kt = k0; kt < k1; kt += 128) {
        int kc = min(128, k1 - kt);
        __syncthreads();
        for (int i = threadIdx.x; i < 16 * 128; i += 256) {
            int b = i >> 7, kk = i & 127;
            if (kk < kc) fs[kk * 16 + b] = fin[b * K + kt + kk];
        }
        __syncthreads();

        const float* wp = W + (size_t)kt * N;
#pragma unroll 4
        for (int kk = 0; kk < kc; kk++) {
            const float* wr = wp + (size_t)kk * N;
            float w0 = wr[nc[0]], w1 = wr[nc[1]], w2 = wr[nc[2]], w3 = wr[nc[3]];
            unsigned long long p0, p1, p2, p3;
            asm("mov.b64 %0, {%1, %1};" : "=l"(p0) : "f"(w0));
            asm("mov.b64 %0, {%1, %1};" : "=l"(p1) : "f"(w1));
            asm("mov.b64 %0, {%1, %1};" : "=l"(p2) : "f"(w2));
            asm("mov.b64 %0, {%1, %1};" : "=l"(p3) : "f"(w3));
            const unsigned long long* f2 = (const unsigned long long*)&fs[kk * 16];
#pragma unroll
            for (int p = 0; p < 8; p++) {
                unsigned long long fv = f2[p];
                FMA_F32X2(acc[p],      p0, fv);
                FMA_F32X2(acc[8 + p],  p1, fv);
                FMA_F32X2(acc[16 + p], p2, fv);
                FMA_F32X2(acc[24 + p], p3, fv);
            }
        }
    }

#pragma unroll
    for (int c = 0; c < 4; c++) {
        if (vld[c]) {
#pragma unroll
            for (int p = 0; p < 8; p++) {
                unsigned long long a = acc[c * 8 + p];
                float lo = __uint_as_float((unsigned int)a);
                float hi = __uint_as_float((unsigned int)(a >> 32));
                g_fcpart[(size_t)(s * 16 + 2 * p + 0) * N + nc[c]] = lo;
                g_fcpart[(size_t)(s * 16 + 2 * p + 1) * N + nc[c]] = hi;
            }
        }
    }
}

// deterministic k-split reduction + bias.
// out_sel: 0 -> g_f1, 1 -> g_f2, 2 -> harness out pointer (recon region)
__global__ void k_reduce(const float* __restrict__ bias,
                         int N, int S, int out_sel, float* __restrict__ hout) {
    float* out = (out_sel == 0) ? g_f1 : (out_sel == 1) ? g_f2 : hout;
    int idx = blockIdx.x * 256 + threadIdx.x;
    if (idx < 16 * N) {
        int b = idx / N, n = idx - b * N;
        float s = bias[n];
        for (int sp = 0; sp < S; sp++) s += g_fcpart[(size_t)(sp * 16 + b) * N + n];
        out[b * N + n] = s;
    }
}

// ---------------- launcher ----------------
extern "C" void kernel_launch(void* const* d_in, const int* in_sizes, int n_in,
                              void* d_out, int out_size) {
    const float* x      = (const float*)d_in[0];
    const float* conv_w = (const float*)d_in[1];
    const float* conv_b = (const float*)d_in[2];
    const float* W_caps = (const float*)d_in[3];
    const float* fc1_w  = (const float*)d_in[4];
    const float* fc1_b  = (const float*)d_in[5];
    const float* fc2_w  = (const float*)d_in[6];
    const float* fc2_b  = (const float*)d_in[7];
    const float* fc3_w  = (const float*)d_in[8];
    const float* fc3_b  = (const float*)d_in[9];
    float* out = (float*)d_out;

    (void)in_sizes; (void)n_in; (void)out_size;

    k_transpose_w<<<927, 256>>>(conv_w);
    k_wsum<<<1648, 256>>>(W_caps);
    k_initb<<<(NOUT * CCONV + 255) / 256, 256>>>();
    k_conv<<<dim3(NCH, 16), 256>>>(x);
    k_relu_sum<<<(Bsz * CCONV * 49 + 255) / 256, 256>>>(conv_b);
    k_squash_p<<<16, 256>>>();

    for (int it = 0; it < 3; it++) {
        k_route_sj<<<103, 256>>>();
        k_route_v<<<16, 256>>>();
        if (it < 2) k_route_update<<<103, 256>>>();
    }
    k_ba_f0<<<7, 256>>>(out);

    // fc1: (16x1648)@(1648x5562)   tiles=6,  S=26 (chunk 64)  -> 156 blocks
    k_gemm4<<<dim3(6, 26), 256>>>(0, fc1_w, H1N, F0N, 64);
    k_reduce<<<(16 * H1N + 255) / 256, 256>>>(fc1_b, H1N, 26, 0, out);
    // fc2: (16x5562)@(5562x12514)  tiles=13, S=23 (chunk 242) -> 299 blocks
    k_gemm4<<<dim3(13, 23), 256>>>(1, fc2_w, H2N, H1N, 242);
    k_reduce<<<(16 * H2N + 255) / 256, 256>>>(fc2_b, H2N, 23, 1, out);
    // fc3: (16x12514)@(12514x8343) tiles=9,  S=33 (chunk 380) -> 297 blocks
    k_gemm4<<<dim3(9, 33), 256>>>(2, fc3_w, RECN, H2N, 380);
    k_reduce<<<(16 * RECN + 255) / 256, 256>>>(fc3_b, RECN, 33, 2, out + Bsz * NOUT);
}